// round 1
// baseline (speedup 1.0000x reference)
#include <cuda_runtime.h>
#include <cuda_bf16.h>

// DistortionLoss (eff_distloss) for GB300.
// Inputs (metadata order): weights [B,128] f32, distances [B,128] f32, intervals [B,128] f32.
// Output: scalar f32 = LOSS_WEIGHT * mean_over_rays( (1/3)*sum s*w^2 + 2*sum_i (wm_i*exW_i - w_i*exWM_i) )
// where exW_i / exWM_i are EXCLUSIVE prefix sums of w and w*m within the row.
//
// Strategy: one row per warp. Each lane loads float4 (4 elements) of each of
// the 3 inputs -> fully coalesced 512B/warp/input. Row cumsum = local serial
// prefix over 4 elems + 5-step __shfl_up warp scan (w and wm scanned together).
// Reduction: lane fp32 acc over grid-strided rows -> warp shuffle reduce ->
// block smem reduce -> one atomicAdd(double) per block into a __device__
// global. Finalize kernel scales and writes the fp32 scalar.

#define LOSS_WEIGHT 0.01f
#define N_SAMPLES 128

__device__ double g_accum;

__global__ void dl_zero_kernel() {
    g_accum = 0.0;
}

__global__ __launch_bounds__(256) void dl_main_kernel(
    const float* __restrict__ w,
    const float* __restrict__ m,
    const float* __restrict__ s,
    int B)
{
    const int lane   = threadIdx.x & 31;
    const int warpIn = threadIdx.x >> 5;
    const int gwarp  = (blockIdx.x * blockDim.x + threadIdx.x) >> 5;
    const int nwarps = (gridDim.x * blockDim.x) >> 5;

    float acc = 0.0f;

    for (int row = gwarp; row < B; row += nwarps) {
        const size_t base = (size_t)row * N_SAMPLES;
        const float4 wv = reinterpret_cast<const float4*>(w + base)[lane];
        const float4 mv = reinterpret_cast<const float4*>(m + base)[lane];
        const float4 sv = reinterpret_cast<const float4*>(s + base)[lane];

        // uni term partial: sum s*w^2 over this lane's 4 elements
        float uni = sv.x * wv.x * wv.x;
        uni = fmaf(sv.y * wv.y, wv.y, uni);
        uni = fmaf(sv.z * wv.z, wv.z, uni);
        uni = fmaf(sv.w * wv.w, wv.w, uni);

        // wm = w * m
        const float wm0 = wv.x * mv.x;
        const float wm1 = wv.y * mv.y;
        const float wm2 = wv.z * mv.z;
        const float wm3 = wv.w * mv.w;

        // local exclusive prefixes within the 4-element chunk
        const float eW1 = wv.x;
        const float eW2 = eW1 + wv.y;
        const float eW3 = eW2 + wv.z;
        const float tW  = eW3 + wv.w;     // lane total of w

        const float eM1 = wm0;
        const float eM2 = eM1 + wm1;
        const float eM3 = eM2 + wm2;
        const float tM  = eM3 + wm3;      // lane total of wm

        // warp inclusive scan of lane totals (w and wm together)
        float iW = tW, iM = tM;
        #pragma unroll
        for (int off = 1; off < 32; off <<= 1) {
            const float aW = __shfl_up_sync(0xffffffffu, iW, off);
            const float aM = __shfl_up_sync(0xffffffffu, iM, off);
            if (lane >= off) { iW += aW; iM += aM; }
        }
        const float EW = iW - tW;   // exclusive warp prefix of w
        const float EM = iM - tM;   // exclusive warp prefix of wm

        // bi term: sum_k wm_k * exW_k - w_k * exWM_k  (exclusive prefixes)
        float bi;
        bi  = wm0 * EW          - wv.x * EM;
        bi += wm1 * (EW + eW1)  - wv.y * (EM + eM1);
        bi += wm2 * (EW + eW2)  - wv.z * (EM + eM2);
        bi += wm3 * (EW + eW3)  - wv.w * (EM + eM3);

        acc += (1.0f / 3.0f) * uni + 2.0f * bi;
    }

    // warp reduce
    #pragma unroll
    for (int off = 16; off > 0; off >>= 1)
        acc += __shfl_down_sync(0xffffffffu, acc, off);

    __shared__ float warp_sums[8];
    if (lane == 0) warp_sums[warpIn] = acc;
    __syncthreads();

    if (threadIdx.x == 0) {
        float blockAcc = 0.0f;
        #pragma unroll
        for (int i = 0; i < 8; i++) blockAcc += warp_sums[i];
        atomicAdd(&g_accum, (double)blockAcc);
    }
}

__global__ void dl_finalize_kernel(float* __restrict__ out, float scale) {
    out[0] = (float)(g_accum * (double)scale);
}

extern "C" void kernel_launch(void* const* d_in, const int* in_sizes, int n_in,
                              void* d_out, int out_size) {
    const float* w = (const float*)d_in[0];
    const float* m = (const float*)d_in[1];
    const float* s = (const float*)d_in[2];
    float* out = (float*)d_out;

    const int B = in_sizes[0] / N_SAMPLES;

    dl_zero_kernel<<<1, 1>>>();

    // 4096 blocks x 256 threads = 32768 warps -> 8 rows/warp at B=262144
    const int threads = 256;
    int blocks = (B + 7) / 8;            // one warp per 8 rows
    if (blocks > 4096) blocks = 4096;
    if (blocks < 1) blocks = 1;
    dl_main_kernel<<<blocks, threads>>>(w, m, s, B);

    dl_finalize_kernel<<<1, 1>>>(out, LOSS_WEIGHT / (float)B);
}